// round 7
// baseline (speedup 1.0000x reference)
#include <cuda_runtime.h>
#include <cuda_bf16.h>
#include <cstdint>

#define BB   64
#define EMBD 256
#define HIDD 512
#define VOC  32000
#define TT   64

typedef unsigned long long ull;

// ---------------- scratch (device globals; no allocation) ----------------
__device__ __align__(16) float g_hbuf[2][BB * HIDD];
__device__ __align__(16) float g_cbuf[BB * HIDD];
__device__ __align__(16) __nv_bfloat16 g_habf16[128 * HIDD];   // rows 0..63 h_hi, 64..127 h_lo
__device__ __align__(16) __nv_bfloat16 g_whi[(size_t)VOC * HIDD];
__device__ __align__(16) __nv_bfloat16 g_wlo[(size_t)VOC * HIDD];
__device__ ull  g_amaxA[BB];
__device__ int  g_tok[TT][BB];
__device__ int  g_tmode[1];

// ---------------- scalar helpers ----------------
__device__ __forceinline__ ull ffma2(ull a, ull b, ull c) {
    ull d;
    asm("fma.rn.f32x2 %0, %1, %2, %3;" : "=l"(d) : "l"(a), "l"(b), "l"(c));
    return d;
}
__device__ __forceinline__ float sigm_acc(float x) { return 1.0f / (2.0f + expm1f(-x)); }
__device__ __forceinline__ float tanh_acc(float x) {
    float ax = fabsf(x);
    if (ax > 9.0f) return copysignf(1.0f, x);
    float e = expm1f(2.0f * ax);
    return copysignf(e / (e + 2.0f), x);
}
__device__ __forceinline__ ull pack_key(float v, int n) {
    unsigned u = __float_as_uint(v);
    u = (u & 0x80000000u) ? ~u : (u | 0x80000000u);
    return ((ull)u << 32) | (ull)(0xFFFFFFFFu - (unsigned)n);
}
__device__ __forceinline__ float unpack_val(ull key) {
    unsigned u = (unsigned)(key >> 32);
    return (u & 0x80000000u) ? __uint_as_float(u ^ 0x80000000u) : __uint_as_float(~u);
}
__device__ __forceinline__ uint32_t smem_u32(const void* p) {
    uint32_t a;
    asm("{ .reg .u64 t; cvta.to.shared.u64 t, %1; cvt.u32.u64 %0, t; }" : "=r"(a) : "l"(p));
    return a;
}

// ---------------- mma / ldmatrix / cp.async (arch-portable, sm_80+) ----------
#define SWZ(o) ((o) ^ (((o) >> 3) & 0x70))
#define LDSM4(r0, r1, r2, r3, addr) \
    asm volatile("ldmatrix.sync.aligned.m8n8.x4.shared.b16 {%0,%1,%2,%3}, [%4];" \
        : "=r"(r0), "=r"(r1), "=r"(r2), "=r"(r3) : "r"(addr))
#define MMA16816(d, a, b0, b1) \
    asm volatile("mma.sync.aligned.m16n8k16.row.col.f32.bf16.bf16.f32 " \
        "{%0,%1,%2,%3},{%4,%5,%6,%7},{%8,%9},{%0,%1,%2,%3};" \
        : "+f"((d)[0]), "+f"((d)[1]), "+f"((d)[2]), "+f"((d)[3]) \
        : "r"((a)[0]), "r"((a)[1]), "r"((a)[2]), "r"((a)[3]), "r"(b0), "r"(b1))
#define CPASYNC16(dst, src) \
    asm volatile("cp.async.cg.shared.global [%0], [%1], 16;" :: "r"(dst), "l"(src) : "memory")
#define CP_COMMIT() asm volatile("cp.async.commit_group;" ::: "memory")
#define CP_WAIT1()  asm volatile("cp.async.wait_group 1;" ::: "memory")
#define CP_WAIT0()  asm volatile("cp.async.wait_group 0;" ::: "memory")

// ---------------- init ----------------
__global__ void init_kernel(const float* __restrict__ eh, const float* __restrict__ ec,
                            const int* __restrict__ tgt_i32) {
    int idx = blockIdx.x * blockDim.x + threadIdx.x;
    if (idx < BB * HIDD) {
        g_hbuf[0][idx] = eh[idx];
        g_cbuf[idx]    = ec[idx];
    }
    if (idx < BB) g_amaxA[idx] = 0ull;
    if (idx == 0)
        g_tmode[0] = ((tgt_i32[1] | tgt_i32[3] | tgt_i32[5] | tgt_i32[7]) == 0) ? 1 : 0;
}

// ---------------- fc_w -> bf16 hi/lo split (once per call) ----------------
__global__ void __launch_bounds__(256) wsplit_kernel(const float* __restrict__ fc_w) {
    size_t i4 = (size_t)blockIdx.x * 256 + threadIdx.x;     // grid 16000 exact
    float4 v = ((const float4*)fc_w)[i4];
    __nv_bfloat16 h0 = __float2bfloat16(v.x), h1 = __float2bfloat16(v.y),
                  h2 = __float2bfloat16(v.z), h3 = __float2bfloat16(v.w);
    __nv_bfloat16 l0 = __float2bfloat16(v.x - __bfloat162float(h0));
    __nv_bfloat16 l1 = __float2bfloat16(v.y - __bfloat162float(h1));
    __nv_bfloat16 l2 = __float2bfloat16(v.z - __bfloat162float(h2));
    __nv_bfloat16 l3 = __float2bfloat16(v.w - __bfloat162float(h3));
    uint2 H, L;
    H.x = (uint32_t)__bfloat16_as_ushort(h0) | ((uint32_t)__bfloat16_as_ushort(h1) << 16);
    H.y = (uint32_t)__bfloat16_as_ushort(h2) | ((uint32_t)__bfloat16_as_ushort(h3) << 16);
    L.x = (uint32_t)__bfloat16_as_ushort(l0) | ((uint32_t)__bfloat16_as_ushort(l1) << 16);
    L.y = (uint32_t)__bfloat16_as_ushort(l2) | ((uint32_t)__bfloat16_as_ushort(l3) << 16);
    ((uint2*)g_whi)[i4] = H;
    ((uint2*)g_wlo)[i4] = L;
}

// ---------------- gates + LSTM pointwise (R4-proven) ----------------
#define G_SMEM_BYTES (197120 + 256)

__global__ void __launch_bounds__(256)
gates_kernel(int t,
             const long long* __restrict__ tgt64, const int* __restrict__ tgt32,
             const int* __restrict__ tf_mask,
             const float* __restrict__ emb,
             const float* __restrict__ w_ih, const float* __restrict__ w_hh,
             const float* __restrict__ b_ih, const float* __restrict__ b_hh) {
    extern __shared__ char smem[];
    ulonglong2* s_hx = (ulonglong2*)smem;
    ulonglong2* s_w  = (ulonglong2*)(smem + 131072);
    float (*s_part)[16][65] = (float (*)[16][65])(smem + 163840);
    int* s_inp = (int*)(smem + 197120);

    const int tid  = threadIdx.x;
    const int j0   = blockIdx.x * 4;
    const int w    = tid >> 5;
    const int lane = tid & 31;
    const int mg   = lane >> 2;
    const int rq   = lane & 3;

    if (tid < BB) {
        int inp = 0;
        if (t > 0) {
            if (tf_mask[t - 1] > 0) {
                inp = g_tmode[0] ? (int)tgt64[(size_t)tid * TT + (t - 1)]
                                 : tgt32[(size_t)tid * TT + (t - 1)];
            } else {
                inp = g_tok[t - 1][tid];
            }
        }
        s_inp[tid] = inp;
    }
    __syncthreads();

    ull acc[8][4];
#pragma unroll
    for (int i = 0; i < 8; ++i)
#pragma unroll
        for (int j = 0; j < 4; ++j) acc[i][j] = 0ull;

    // phase 1: embedding, K=256
#pragma unroll
    for (int it = 0; it < 16; ++it) {
        int idx = tid + it * 256;
        int m = idx >> 6, kq = idx & 63;
        float4 v = *(const float4*)&emb[(size_t)s_inp[m] * EMBD + kq * 4];
        s_hx[m * 64 + (kq ^ (m >> 3))] = *(ulonglong2*)&v;
    }
#pragma unroll
    for (int it = 0; it < 4; ++it) {
        int idx = tid + it * 256;
        int rr = idx >> 6, kq = idx & 63;
        int R  = (rr >> 2) * HIDD + j0 + (rr & 3);
        float4 v = *(const float4*)&w_ih[(size_t)R * EMBD + kq * 4];
        s_w[rr * 64 + (kq ^ (rr >> 2))] = *(ulonglong2*)&v;
    }
    __syncthreads();
#pragma unroll
    for (int q8 = 0; q8 < 8; ++q8) {
        int q = w * 8 + q8;
        ulonglong2 xv[8], wv[4];
#pragma unroll
        for (int i = 0; i < 8; ++i) xv[i] = s_hx[(mg * 8 + i) * 64 + (q ^ mg)];
#pragma unroll
        for (int j = 0; j < 4; ++j) wv[j] = s_w[(rq * 4 + j) * 64 + (q ^ rq)];
#pragma unroll
        for (int i = 0; i < 8; ++i)
#pragma unroll
            for (int j = 0; j < 4; ++j) {
                acc[i][j] = ffma2(xv[i].x, wv[j].x, acc[i][j]);
                acc[i][j] = ffma2(xv[i].y, wv[j].y, acc[i][j]);
            }
    }
    __syncthreads();

    // phase 2: h_prev, K=512
    const float* __restrict__ hprev = g_hbuf[t & 1];
#pragma unroll
    for (int it = 0; it < 32; ++it) {
        int idx = tid + it * 256;
        int m = idx >> 7, kq = idx & 127;
        float4 v = *(const float4*)&hprev[(size_t)m * HIDD + kq * 4];
        s_hx[m * 128 + (kq ^ (m >> 3))] = *(ulonglong2*)&v;
    }
#pragma unroll
    for (int it = 0; it < 8; ++it) {
        int idx = tid + it * 256;
        int rr = idx >> 7, kq = idx & 127;
        int R  = (rr >> 2) * HIDD + j0 + (rr & 3);
        float4 v = *(const float4*)&w_hh[(size_t)R * HIDD + kq * 4];
        s_w[rr * 128 + (kq ^ (rr >> 2))] = *(ulonglong2*)&v;
    }
    __syncthreads();
#pragma unroll
    for (int q16 = 0; q16 < 16; ++q16) {
        int q = w * 16 + q16;
        ulonglong2 xv[8], wv[4];
#pragma unroll
        for (int i = 0; i < 8; ++i) xv[i] = s_hx[(mg * 8 + i) * 128 + (q ^ mg)];
#pragma unroll
        for (int j = 0; j < 4; ++j) wv[j] = s_w[(rq * 4 + j) * 128 + (q ^ rq)];
#pragma unroll
        for (int i = 0; i < 8; ++i)
#pragma unroll
            for (int j = 0; j < 4; ++j) {
                acc[i][j] = ffma2(xv[i].x, wv[j].x, acc[i][j]);
                acc[i][j] = ffma2(xv[i].y, wv[j].y, acc[i][j]);
            }
    }

#pragma unroll
    for (int i = 0; i < 8; ++i)
#pragma unroll
        for (int j = 0; j < 4; ++j) {
            float2 p = *(float2*)&acc[i][j];
            s_part[w][rq * 4 + j][mg * 8 + i] = p.x + p.y;
        }
    __syncthreads();

    {
        int m  = tid & 63;
        int jj = tid >> 6;
        float gv4[4];
#pragma unroll
        for (int g = 0; g < 4; ++g) {
            float s = 0.f;
#pragma unroll
            for (int w8 = 0; w8 < 8; ++w8) s += s_part[w8][g * 4 + jj][m];
            int R = g * HIDD + j0 + jj;
            gv4[g] = s + b_ih[R] + b_hh[R];
        }
        float iv = sigm_acc(gv4[0]);
        float fv = sigm_acc(gv4[1]);
        float gg = tanh_acc(gv4[2]);
        float ov = sigm_acc(gv4[3]);
        int j = j0 + jj;
        float c0 = g_cbuf[(size_t)m * HIDD + j];
        float c1 = fv * c0 + iv * gg;
        float h1 = ov * tanh_acc(c1);
        g_cbuf[(size_t)m * HIDD + j]              = c1;
        g_hbuf[(t + 1) & 1][(size_t)m * HIDD + j] = h1;
        __nv_bfloat16 hi = __float2bfloat16(h1);
        g_habf16[(size_t)m * HIDD + j]        = hi;
        g_habf16[(size_t)(m + 64) * HIDD + j] =
            __float2bfloat16(h1 - __bfloat162float(hi));
    }
}

// ---------------- fc via mma.sync bf16 split (fused approx argmax) -----------
// grid 125 (N-tile 256), block 512 = 16 warps (wm = w&3 m-group, wn = w>>2 n-group).
// Warp tile: m-frags = rows {wm*16..+15} (hi) and {+64} (lo) x 64 n.
// K chunks of 64, cp.async double buffer, 2 passes (W_hi then W_lo), fold in regs.
// smem: A[2] 2x16KB @0, W[2] 2x32KB @32768, bias @98304, amax @99328.
#define FC_SMEM 99904
#define OFF_A(b) ((b) * 16384)
#define OFF_W(b) (32768 + (b) * 32768)

__global__ void __launch_bounds__(512)
fc_mma_kernel(int t, const float* __restrict__ fc_b, float* __restrict__ out) {
    extern __shared__ char smem[];
    const uint32_t sbase = smem_u32(smem);
    float* s_bias = (float*)(smem + 98304);
    ull*   s_amax = (ull*)(smem + 99328);

    const int tid  = threadIdx.x;
    const int w    = tid >> 5;
    const int lane = tid & 31;
    const int wm   = w & 3;
    const int wn   = w >> 2;
    const int nb   = blockIdx.x;
    const int row16 = lane & 15;
    const int kseg  = lane >> 4;

    if (tid < 256) s_bias[tid] = fc_b[nb * 256 + tid];
    if (tid < 64)  s_amax[tid] = 0ull;

    float acc[2][8][4];
#pragma unroll
    for (int mi = 0; mi < 2; ++mi)
#pragma unroll
        for (int fj = 0; fj < 8; ++fj)
#pragma unroll
            for (int e = 0; e < 4; ++e) acc[mi][fj][e] = 0.f;

    // ---- async load issue for chunk c ----
    auto issue = [&](int c) {
        int buf = c & 1;
        int kc  = (c & 7) * 64;
        const __nv_bfloat16* wsrc = (c < 8) ? g_whi : g_wlo;
#pragma unroll
        for (int i = 0; i < 2; ++i) {
            int s = tid + i * 512;
            int row = s >> 3, ks = s & 7;
            uint32_t dst = sbase + OFF_A(buf) + SWZ((uint32_t)(row * 128 + ks * 16));
            CPASYNC16(dst, &g_habf16[(size_t)row * HIDD + kc + ks * 8]);
        }
#pragma unroll
        for (int i = 0; i < 4; ++i) {
            int s = tid + i * 512;
            int row = s >> 3, ks = s & 7;
            uint32_t dst = sbase + OFF_W(buf) + SWZ((uint32_t)(row * 128 + ks * 16));
            CPASYNC16(dst, &wsrc[((size_t)(nb * 256 + row)) * HIDD + kc + ks * 8]);
        }
        CP_COMMIT();
    };

    issue(0);
    for (int c = 0; c < 16; ++c) {
        if (c + 1 < 16) { issue(c + 1); CP_WAIT1(); }
        else            { CP_WAIT0(); }
        __syncthreads();
        int buf = c & 1;
        const uint32_t aBase = sbase + OFF_A(buf);
        const uint32_t wBase = sbase + OFF_W(buf);
#pragma unroll
        for (int kf = 0; kf < 4; ++kf) {
            uint32_t aH[4], aL[4];
            LDSM4(aH[0], aH[1], aH[2], aH[3],
                  aBase + SWZ((uint32_t)((wm * 16 + row16) * 128 + kf * 32 + kseg * 16)));
            LDSM4(aL[0], aL[1], aL[2], aL[3],
                  aBase + SWZ((uint32_t)((64 + wm * 16 + row16) * 128 + kf * 32 + kseg * 16)));
#pragma unroll
            for (int j = 0; j < 4; ++j) {
                uint32_t b[4];
                LDSM4(b[0], b[1], b[2], b[3],
                      wBase + SWZ((uint32_t)((wn * 64 + j * 16 + row16) * 128 + kf * 32 + kseg * 16)));
                MMA16816(acc[0][j * 2 + 0], aH, b[0], b[2]);
                MMA16816(acc[0][j * 2 + 1], aH, b[1], b[3]);
                MMA16816(acc[1][j * 2 + 0], aL, b[0], b[2]);
                MMA16816(acc[1][j * 2 + 1], aL, b[1], b[3]);
            }
        }
        __syncthreads();
    }

    // ---- epilogue: fold hi+lo, bias, store, approx argmax keys ----
    const int r0 = wm * 16 + (lane >> 2);          // batch rows r0, r0+8
    ull best0 = 0ull, best1 = 0ull;
#pragma unroll
    for (int fj = 0; fj < 8; ++fj) {
        int cb = wn * 64 + fj * 8 + (lane & 3) * 2;     // block-local col
        int n  = nb * 256 + cb;
        float v0 = acc[0][fj][0] + acc[1][fj][0] + s_bias[cb];
        float v1 = acc[0][fj][1] + acc[1][fj][1] + s_bias[cb + 1];
        float v2 = acc[0][fj][2] + acc[1][fj][2] + s_bias[cb];
        float v3 = acc[0][fj][3] + acc[1][fj][3] + s_bias[cb + 1];
        *(float2*)&out[((size_t)r0 * TT + t) * VOC + n]       = make_float2(v0, v1);
        *(float2*)&out[((size_t)(r0 + 8) * TT + t) * VOC + n] = make_float2(v2, v3);
        ull k0 = pack_key(v0, n), k1 = pack_key(v1, n + 1);
        ull k2 = pack_key(v2, n), k3 = pack_key(v3, n + 1);
        if (k1 > k0) k0 = k1;
        if (k3 > k2) k2 = k3;
        if (k0 > best0) best0 = k0;
        if (k2 > best1) best1 = k2;
    }
    atomicMax(&s_amax[r0], best0);
    atomicMax(&s_amax[r0 + 8], best1);
    __syncthreads();
    if (tid < 64) atomicMax(&g_amaxA[tid], s_amax[tid]);
}

// ---------------- argmax fixup: exact fp32 re-check of near-max candidates ---
__global__ void __launch_bounds__(256)
fixup_kernel(int t, const float* __restrict__ fc_w, const float* __restrict__ fc_b,
             const float* __restrict__ out) {
    __shared__ float s_h[HIDD];
    __shared__ ull s_red[256];
    const int m = blockIdx.x, tid = threadIdx.x;
    const float* hsrc = g_hbuf[(t + 1) & 1] + (size_t)m * HIDD;
    s_h[tid] = hsrc[tid];
    s_h[256 + tid] = hsrc[256 + tid];
    __syncthreads();
    const float thresh = unpack_val(g_amaxA[m]) - 1e-2f;
    const float* row = out + ((size_t)m * TT + t) * VOC;
    ull best = 0ull;
    for (int n = tid; n < VOC; n += 256) {
        float v = row[n];
        if (v >= thresh) {
            const ull* hp = (const ull*)s_h;
            const ull* wp = (const ull*)(fc_w + (size_t)n * HIDD);
            ull acc = 0ull;
#pragma unroll 8
            for (int i = 0; i < 256; ++i) acc = ffma2(hp[i], wp[i], acc);
            float2 p = *(float2*)&acc;
            ull key = pack_key(p.x + p.y + fc_b[n], n);
            if (key > best) best = key;
        }
    }
    s_red[tid] = best;
    __syncthreads();
    for (int s = 128; s > 0; s >>= 1) {
        if (tid < s && s_red[tid + s] > s_red[tid]) s_red[tid] = s_red[tid + s];
        __syncthreads();
    }
    if (tid == 0) {
        g_tok[t][m] = (int)(0xFFFFFFFFu - (unsigned)(s_red[0] & 0xFFFFFFFFull));
        g_amaxA[m] = 0ull;
    }
}

// ---------------- final h/c tail ----------------
__global__ void final_kernel(float* __restrict__ out, int out_size) {
    int idx = blockIdx.x * blockDim.x + threadIdx.x;
    const size_t base = (size_t)BB * TT * VOC;
    if ((size_t)out_size >= base + 2ull * BB * HIDD) {
        if (idx < BB * HIDD) {
            out[base + idx]             = g_hbuf[0][idx];
            out[base + BB * HIDD + idx] = g_cbuf[idx];
        }
    }
}

// ---------------- launch ----------------
extern "C" void kernel_launch(void* const* d_in, const int* in_sizes, int n_in,
                              void* d_out, int out_size) {
    const float* encoder_h = (const float*)d_in[0];
    const float* encoder_c = (const float*)d_in[1];
    const void*  target    = d_in[2];
    const int*   tf_mask   = (const int*)d_in[3];
    const float* embedding = (const float*)d_in[4];
    const float* w_ih      = (const float*)d_in[5];
    const float* w_hh      = (const float*)d_in[6];
    const float* b_ih      = (const float*)d_in[7];
    const float* b_hh      = (const float*)d_in[8];
    const float* fc_w      = (const float*)d_in[9];
    const float* fc_b      = (const float*)d_in[10];
    float* out = (float*)d_out;

    cudaFuncSetAttribute(gates_kernel,
                         cudaFuncAttributeMaxDynamicSharedMemorySize, G_SMEM_BYTES);
    cudaFuncSetAttribute(fc_mma_kernel,
                         cudaFuncAttributeMaxDynamicSharedMemorySize, FC_SMEM);

    init_kernel<<<128, 256>>>(encoder_h, encoder_c, (const int*)target);
    wsplit_kernel<<<16000, 256>>>(fc_w);
    for (int t = 0; t < TT; ++t) {
        gates_kernel<<<128, 256, G_SMEM_BYTES>>>(t, (const long long*)target,
                                                 (const int*)target, tf_mask, embedding,
                                                 w_ih, w_hh, b_ih, b_hh);
        fc_mma_kernel<<<125, 512, FC_SMEM>>>(t, fc_b, out);
        fixup_kernel<<<64, 256>>>(t, fc_w, fc_b, out);
    }
    final_kernel<<<128, 256>>>(out, out_size);
}

// round 8
// speedup vs baseline: 1.4398x; 1.4398x over previous
#include <cuda_runtime.h>
#include <cuda_bf16.h>
#include <cstdint>

#define BB   64
#define EMBD 256
#define HIDD 512
#define VOC  32000
#define TT   64

typedef unsigned long long ull;

// ---------------- scratch (device globals; no allocation) ----------------
__device__ __align__(16) float g_hbuf[2][BB * HIDD];
__device__ __align__(16) float g_cbuf[BB * HIDD];
// A operand, chunk-major + pre-swizzled: [kchunk 0..7][16KB chunk]
//   chunk holds rows 0..127 (0-63 h_hi, 64-127 h_lo) x 64 bf16 cols
__device__ __align__(16) __nv_bfloat16 g_habf16[128 * HIDD];
// W operands, chunk-major + pre-swizzled: [nb 0..124][kchunk 0..7][32KB chunk]
//   chunk holds rows 0..255 x 64 bf16 cols
__device__ __align__(16) __nv_bfloat16 g_whi[(size_t)VOC * HIDD];
__device__ __align__(16) __nv_bfloat16 g_wlo[(size_t)VOC * HIDD];
__device__ ull  g_amaxA[TT][BB];   // approx keys (from fc)
__device__ ull  g_amaxE[TT][BB];   // exact keys  (from fixup)
__device__ int  g_tmode[1];

// ---------------- scalar helpers ----------------
__device__ __forceinline__ ull ffma2(ull a, ull b, ull c) {
    ull d;
    asm("fma.rn.f32x2 %0, %1, %2, %3;" : "=l"(d) : "l"(a), "l"(b), "l"(c));
    return d;
}
__device__ __forceinline__ float sigm_acc(float x) { return 1.0f / (2.0f + expm1f(-x)); }
__device__ __forceinline__ float tanh_acc(float x) {
    float ax = fabsf(x);
    if (ax > 9.0f) return copysignf(1.0f, x);
    float e = expm1f(2.0f * ax);
    return copysignf(e / (e + 2.0f), x);
}
__device__ __forceinline__ ull pack_key(float v, int n) {
    unsigned u = __float_as_uint(v);
    u = (u & 0x80000000u) ? ~u : (u | 0x80000000u);
    return ((ull)u << 32) | (ull)(0xFFFFFFFFu - (unsigned)n);
}
__device__ __forceinline__ float unpack_val(ull key) {
    unsigned u = (unsigned)(key >> 32);
    return (u & 0x80000000u) ? __uint_as_float(u ^ 0x80000000u) : __uint_as_float(~u);
}
__device__ __forceinline__ uint32_t smem_u32(const void* p) {
    uint32_t a;
    asm("{ .reg .u64 t; cvta.to.shared.u64 t, %1; cvt.u32.u64 %0, t; }" : "=r"(a) : "l"(p));
    return a;
}

// ---------------- mma / ldmatrix / bulk-async (sm_90 baseline PTX) -----------
#define SWZ(o) ((o) ^ (((o) >> 3) & 0x70))
#define LDSM4(r0, r1, r2, r3, addr) \
    asm volatile("ldmatrix.sync.aligned.m8n8.x4.shared.b16 {%0,%1,%2,%3}, [%4];" \
        : "=r"(r0), "=r"(r1), "=r"(r2), "=r"(r3) : "r"(addr))
#define MMA16816(d, a, b0, b1) \
    asm volatile("mma.sync.aligned.m16n8k16.row.col.f32.bf16.bf16.f32 " \
        "{%0,%1,%2,%3},{%4,%5,%6,%7},{%8,%9},{%0,%1,%2,%3};" \
        : "+f"((d)[0]), "+f"((d)[1]), "+f"((d)[2]), "+f"((d)[3]) \
        : "r"((a)[0]), "r"((a)[1]), "r"((a)[2]), "r"((a)[3]), "r"(b0), "r"(b1))
#define FENCE_ASYNC()     asm volatile("fence.proxy.async.shared::cta;" ::: "memory")
#define MBAR_INIT(mb, c)  asm volatile("mbarrier.init.shared.b64 [%0], %1;" :: "r"(mb), "r"((uint32_t)(c)) : "memory")
#define MBAR_EXPECT_TX(mb, bytes) \
    asm volatile("mbarrier.arrive.expect_tx.shared.b64 _, [%0], %1;" :: "r"(mb), "r"((uint32_t)(bytes)) : "memory")
#define BULK_G2S(dst, src, size, mb) \
    asm volatile("cp.async.bulk.shared::cta.global.mbarrier::complete_tx::bytes [%0], [%1], %2, [%3];" \
        :: "r"(dst), "l"(src), "r"((uint32_t)(size)), "r"(mb) : "memory")
#define MBAR_WAIT(mb, par) do {                                                  \
    uint32_t _mb = (mb), _p = (par), _d;                                         \
    asm volatile("{ .reg .pred p; mbarrier.try_wait.parity.acquire.cta.shared::cta.b64 p, [%1], %2; selp.b32 %0, 1, 0, p; }" \
        : "=r"(_d) : "r"(_mb), "r"(_p) : "memory");                              \
    if (!_d) {                                                                   \
        asm volatile("{ .reg .pred P1; WL_%=: mbarrier.try_wait.parity.acquire.cta.shared::cta.b64 P1, [%0], %1, 0x989680; @P1 bra.uni WD_%=; bra.uni WL_%=; WD_%=: }" \
            :: "r"(_mb), "r"(_p) : "memory");                                    \
    }                                                                            \
} while (0)

// ---------------- init ----------------
__global__ void init_kernel(const float* __restrict__ eh, const float* __restrict__ ec,
                            const int* __restrict__ tgt_i32) {
    int idx = blockIdx.x * blockDim.x + threadIdx.x;
    if (idx < BB * HIDD) {
        g_hbuf[0][idx] = eh[idx];
        g_cbuf[idx]    = ec[idx];
    }
    if (idx < TT * BB) {
        ((ull*)g_amaxA)[idx] = 0ull;
        ((ull*)g_amaxE)[idx] = 0ull;
    }
    if (idx == 0)
        g_tmode[0] = ((tgt_i32[1] | tgt_i32[3] | tgt_i32[5] | tgt_i32[7]) == 0) ? 1 : 0;
}

// ---------------- fc_w -> bf16 hi/lo split, chunk-major + swizzled ----------
// grid 8000, block 256: each thread handles 8 consecutive cols of one row.
__global__ void __launch_bounds__(256) wsplit_kernel(const float* __restrict__ fc_w) {
    size_t u = (size_t)blockIdx.x * 256 + threadIdx.x;    // 0 .. 2,047,999
    int n  = (int)(u >> 6);
    int k8 = (int)(u & 63);
    const float4* src = (const float4*)(fc_w + (size_t)n * HIDD + k8 * 8);
    float4 v0 = src[0], v1 = src[1];
    float f[8] = {v0.x, v0.y, v0.z, v0.w, v1.x, v1.y, v1.z, v1.w};
    unsigned short hw[8], lw[8];
#pragma unroll
    for (int i = 0; i < 8; ++i) {
        __nv_bfloat16 h = __float2bfloat16(f[i]);
        __nv_bfloat16 l = __float2bfloat16(f[i] - __bfloat162float(h));
        hw[i] = __bfloat16_as_ushort(h);
        lw[i] = __bfloat16_as_ushort(l);
    }
    uint4 H, L;
    H.x = hw[0] | ((uint32_t)hw[1] << 16); H.y = hw[2] | ((uint32_t)hw[3] << 16);
    H.z = hw[4] | ((uint32_t)hw[5] << 16); H.w = hw[6] | ((uint32_t)hw[7] << 16);
    L.x = lw[0] | ((uint32_t)lw[1] << 16); L.y = lw[2] | ((uint32_t)lw[3] << 16);
    L.z = lw[4] | ((uint32_t)lw[5] << 16); L.w = lw[6] | ((uint32_t)lw[7] << 16);
    int nb = n >> 8, rown = n & 255, kch = k8 >> 3, ks = k8 & 7;
    size_t cb = ((size_t)nb * 8 + kch) * 32768;
    uint32_t off = SWZ((uint32_t)(rown * 128 + ks * 16));
    *(uint4*)((char*)g_whi + cb + off) = H;
    *(uint4*)((char*)g_wlo + cb + off) = L;
}

// ---------------- gates + LSTM pointwise (R4-proven core) ----------------
#define G_SMEM_BYTES (197120 + 256)

__global__ void __launch_bounds__(256)
gates_kernel(int t,
             const long long* __restrict__ tgt64, const int* __restrict__ tgt32,
             const int* __restrict__ tf_mask,
             const float* __restrict__ emb,
             const float* __restrict__ w_ih, const float* __restrict__ w_hh,
             const float* __restrict__ b_ih, const float* __restrict__ b_hh) {
    extern __shared__ char smem[];
    ulonglong2* s_hx = (ulonglong2*)smem;
    ulonglong2* s_w  = (ulonglong2*)(smem + 131072);
    float (*s_part)[16][65] = (float (*)[16][65])(smem + 163840);
    int* s_inp = (int*)(smem + 197120);

    const int tid  = threadIdx.x;
    const int j0   = blockIdx.x * 4;
    const int w    = tid >> 5;
    const int lane = tid & 31;
    const int mg   = lane >> 2;
    const int rq   = lane & 3;

    if (tid < BB) {
        int inp = 0;
        if (t > 0) {
            if (tf_mask[t - 1] > 0) {
                inp = g_tmode[0] ? (int)tgt64[(size_t)tid * TT + (t - 1)]
                                 : tgt32[(size_t)tid * TT + (t - 1)];
            } else {
                ull p = g_amaxE[t - 1][tid];
                inp = (int)(0xFFFFFFFFu - (unsigned)(p & 0xFFFFFFFFull));
            }
        }
        s_inp[tid] = inp;
    }
    __syncthreads();

    ull acc[8][4];
#pragma unroll
    for (int i = 0; i < 8; ++i)
#pragma unroll
        for (int j = 0; j < 4; ++j) acc[i][j] = 0ull;

    // phase 1: embedding, K=256
#pragma unroll
    for (int it = 0; it < 16; ++it) {
        int idx = tid + it * 256;
        int m = idx >> 6, kq = idx & 63;
        float4 v = *(const float4*)&emb[(size_t)s_inp[m] * EMBD + kq * 4];
        s_hx[m * 64 + (kq ^ (m >> 3))] = *(ulonglong2*)&v;
    }
#pragma unroll
    for (int it = 0; it < 4; ++it) {
        int idx = tid + it * 256;
        int rr = idx >> 6, kq = idx & 63;
        int R  = (rr >> 2) * HIDD + j0 + (rr & 3);
        float4 v = *(const float4*)&w_ih[(size_t)R * EMBD + kq * 4];
        s_w[rr * 64 + (kq ^ (rr >> 2))] = *(ulonglong2*)&v;
    }
    __syncthreads();
#pragma unroll
    for (int q8 = 0; q8 < 8; ++q8) {
        int q = w * 8 + q8;
        ulonglong2 xv[8], wv[4];
#pragma unroll
        for (int i = 0; i < 8; ++i) xv[i] = s_hx[(mg * 8 + i) * 64 + (q ^ mg)];
#pragma unroll
        for (int j = 0; j < 4; ++j) wv[j] = s_w[(rq * 4 + j) * 64 + (q ^ rq)];
#pragma unroll
        for (int i = 0; i < 8; ++i)
#pragma unroll
            for (int j = 0; j < 4; ++j) {
                acc[i][j] = ffma2(xv[i].x, wv[j].x, acc[i][j]);
                acc[i][j] = ffma2(xv[i].y, wv[j].y, acc[i][j]);
            }
    }
    __syncthreads();

    // phase 2: h_prev, K=512
    const float* __restrict__ hprev = g_hbuf[t & 1];
#pragma unroll
    for (int it = 0; it < 32; ++it) {
        int idx = tid + it * 256;
        int m = idx >> 7, kq = idx & 127;
        float4 v = *(const float4*)&hprev[(size_t)m * HIDD + kq * 4];
        s_hx[m * 128 + (kq ^ (m >> 3))] = *(ulonglong2*)&v;
    }
#pragma unroll
    for (int it = 0; it < 8; ++it) {
        int idx = tid + it * 256;
        int rr = idx >> 7, kq = idx & 127;
        int R  = (rr >> 2) * HIDD + j0 + (rr & 3);
        float4 v = *(const float4*)&w_hh[(size_t)R * HIDD + kq * 4];
        s_w[rr * 128 + (kq ^ (rr >> 2))] = *(ulonglong2*)&v;
    }
    __syncthreads();
#pragma unroll
    for (int q16 = 0; q16 < 16; ++q16) {
        int q = w * 16 + q16;
        ulonglong2 xv[8], wv[4];
#pragma unroll
        for (int i = 0; i < 8; ++i) xv[i] = s_hx[(mg * 8 + i) * 128 + (q ^ mg)];
#pragma unroll
        for (int j = 0; j < 4; ++j) wv[j] = s_w[(rq * 4 + j) * 128 + (q ^ rq)];
#pragma unroll
        for (int i = 0; i < 8; ++i)
#pragma unroll
            for (int j = 0; j < 4; ++j) {
                acc[i][j] = ffma2(xv[i].x, wv[j].x, acc[i][j]);
                acc[i][j] = ffma2(xv[i].y, wv[j].y, acc[i][j]);
            }
    }

#pragma unroll
    for (int i = 0; i < 8; ++i)
#pragma unroll
        for (int j = 0; j < 4; ++j) {
            float2 p = *(float2*)&acc[i][j];
            s_part[w][rq * 4 + j][mg * 8 + i] = p.x + p.y;
        }
    __syncthreads();

    {
        int m  = tid & 63;
        int jj = tid >> 6;
        float gv4[4];
#pragma unroll
        for (int g = 0; g < 4; ++g) {
            float s = 0.f;
#pragma unroll
            for (int w8 = 0; w8 < 8; ++w8) s += s_part[w8][g * 4 + jj][m];
            int R = g * HIDD + j0 + jj;
            gv4[g] = s + b_ih[R] + b_hh[R];
        }
        float iv = sigm_acc(gv4[0]);
        float fv = sigm_acc(gv4[1]);
        float gg = tanh_acc(gv4[2]);
        float ov = sigm_acc(gv4[3]);
        int j = j0 + jj;
        float c0 = g_cbuf[(size_t)m * HIDD + j];
        float c1 = fv * c0 + iv * gg;
        float h1 = ov * tanh_acc(c1);
        g_cbuf[(size_t)m * HIDD + j]              = c1;
        g_hbuf[(t + 1) & 1][(size_t)m * HIDD + j] = h1;
        // A operand write: chunk-major + swizzled (for fc bulk staging)
        __nv_bfloat16 hi = __float2bfloat16(h1);
        __nv_bfloat16 lo = __float2bfloat16(h1 - __bfloat162float(hi));
        int kch = j >> 6, kc = j & 63, ks = kc >> 3, b2 = kc & 7;
        size_t cbase = (size_t)kch * 16384;
        *(__nv_bfloat16*)((char*)g_habf16 + cbase + SWZ((uint32_t)(m * 128 + ks * 16)) + b2 * 2) = hi;
        *(__nv_bfloat16*)((char*)g_habf16 + cbase + SWZ((uint32_t)((m + 64) * 128 + ks * 16)) + b2 * 2) = lo;
    }
}

// ---------------- fc via mma.sync bf16 split + cp.async.bulk staging ---------
// grid 125 (N-tile 256), block 512 = 16 warps. 3-stage bulk pipeline.
// smem: stages [0, 3*49152) | bias @147456 | amax @148480 | mbar[3] @148992
#define FC_STG  49152
#define FC_SMEM 149056

__global__ void __launch_bounds__(512)
fc_mma_kernel(int t, const float* __restrict__ fc_b, float* __restrict__ out) {
    extern __shared__ char smem[];
    const uint32_t sbase = smem_u32(smem);
    float* s_bias = (float*)(smem + 147456);
    ull*   s_amax = (ull*)(smem + 148480);
    const uint32_t mb0 = sbase + 148992;

    const int tid  = threadIdx.x;
    const int w    = tid >> 5;
    const int lane = tid & 31;
    const int wm   = w & 3;
    const int wn   = w >> 2;
    const int nb   = blockIdx.x;
    const int row16 = lane & 15;
    const int kseg  = lane >> 4;

    if (tid < 256) s_bias[tid] = fc_b[nb * 256 + tid];
    if (tid < 64)  s_amax[tid] = 0ull;
    if (tid == 0) { MBAR_INIT(mb0, 1); MBAR_INIT(mb0 + 8, 1); MBAR_INIT(mb0 + 16, 1); }
    __syncthreads();
    FENCE_ASYNC();

    auto issue = [&](int c) {
        int s = c % 3;
        uint32_t mb = mb0 + s * 8;
        MBAR_EXPECT_TX(mb, 49152);
        const char* ap = (const char*)g_habf16 + (size_t)(c & 7) * 16384;
        const char* wp = (const char*)((c < 8) ? g_whi : g_wlo)
                         + ((size_t)nb * 8 + (c & 7)) * 32768;
        BULK_G2S(sbase + s * FC_STG, ap, 16384, mb);
        BULK_G2S(sbase + s * FC_STG + 16384, wp, 32768, mb);
    };
    if (tid == 0) { issue(0); issue(1); issue(2); }

    float acc[2][8][4];
#pragma unroll
    for (int mi = 0; mi < 2; ++mi)
#pragma unroll
        for (int fj = 0; fj < 8; ++fj)
#pragma unroll
            for (int e = 0; e < 4; ++e) acc[mi][fj][e] = 0.f;

    int par[3] = {0, 0, 0};
    for (int c = 0; c < 16; ++c) {
        int s = c % 3;
        MBAR_WAIT(mb0 + s * 8, par[s]);
        par[s] ^= 1;
        const uint32_t aBase = sbase + s * FC_STG;
        const uint32_t wBase = aBase + 16384;
#pragma unroll
        for (int kf = 0; kf < 4; ++kf) {
            uint32_t aH[4], aL[4];
            LDSM4(aH[0], aH[1], aH[2], aH[3],
                  aBase + SWZ((uint32_t)((wm * 16 + row16) * 128 + kf * 32 + kseg * 16)));
            LDSM4(aL[0], aL[1], aL[2], aL[3],
                  aBase + SWZ((uint32_t)((64 + wm * 16 + row16) * 128 + kf * 32 + kseg * 16)));
#pragma unroll
            for (int j = 0; j < 4; ++j) {
                uint32_t b[4];
                LDSM4(b[0], b[1], b[2], b[3],
                      wBase + SWZ((uint32_t)((wn * 64 + j * 16 + row16) * 128 + kf * 32 + kseg * 16)));
                MMA16816(acc[0][j * 2 + 0], aH, b[0], b[2]);
                MMA16816(acc[0][j * 2 + 1], aH, b[1], b[3]);
                MMA16816(acc[1][j * 2 + 0], aL, b[0], b[2]);
                MMA16816(acc[1][j * 2 + 1], aL, b[1], b[3]);
            }
        }
        __syncthreads();
        if (tid == 0 && c + 3 < 16) issue(c + 3);
    }

    // ---- epilogue: fold hi+lo, bias, store, approx argmax keys ----
    const int r0 = wm * 16 + (lane >> 2);
    ull best0 = 0ull, best1 = 0ull;
#pragma unroll
    for (int fj = 0; fj < 8; ++fj) {
        int cb = wn * 64 + fj * 8 + (lane & 3) * 2;
        int n  = nb * 256 + cb;
        float v0 = acc[0][fj][0] + acc[1][fj][0] + s_bias[cb];
        float v1 = acc[0][fj][1] + acc[1][fj][1] + s_bias[cb + 1];
        float v2 = acc[0][fj][2] + acc[1][fj][2] + s_bias[cb];
        float v3 = acc[0][fj][3] + acc[1][fj][3] + s_bias[cb + 1];
        *(float2*)&out[((size_t)r0 * TT + t) * VOC + n]       = make_float2(v0, v1);
        *(float2*)&out[((size_t)(r0 + 8) * TT + t) * VOC + n] = make_float2(v2, v3);
        ull k0 = pack_key(v0, n), k1 = pack_key(v1, n + 1);
        ull k2 = pack_key(v2, n), k3 = pack_key(v3, n + 1);
        if (k1 > k0) k0 = k1;
        if (k3 > k2) k2 = k3;
        if (k0 > best0) best0 = k0;
        if (k2 > best1) best1 = k2;
    }
    atomicMax(&s_amax[r0], best0);
    atomicMax(&s_amax[r0 + 8], best1);
    __syncthreads();
    if (tid < 64) atomicMax(&g_amaxA[t][tid], s_amax[tid]);
}

// ---------------- argmax fixup: exact fp32 re-check, 4 blocks per row --------
__global__ void __launch_bounds__(256)
fixup_kernel(int t, const float* __restrict__ fc_w, const float* __restrict__ fc_b,
             const float* __restrict__ out) {
    __shared__ float s_h[HIDD];
    const int m = blockIdx.x & 63, part = blockIdx.x >> 6, tid = threadIdx.x;
    const float* hsrc = g_hbuf[(t + 1) & 1] + (size_t)m * HIDD;
    s_h[tid] = hsrc[tid];
    s_h[256 + tid] = hsrc[256 + tid];
    __syncthreads();
    const float thresh = unpack_val(g_amaxA[t][m]) - 1e-2f;
    const float* row = out + ((size_t)m * TT + t) * VOC;
    const int lo = part * 8000, hi = lo + 8000;
    ull best = 0ull;
    auto exact = [&](int n) {
        const ull* hp = (const ull*)s_h;
        const ull* wp = (const ull*)(fc_w + (size_t)n * HIDD);
        ull acc = 0ull;
#pragma unroll 8
        for (int i = 0; i < 256; ++i) acc = ffma2(hp[i], wp[i], acc);
        float2 p = *(float2*)&acc;
        ull key = pack_key(p.x + p.y + fc_b[n], n);
        if (key > best) best = key;
    };
    for (int n = lo + tid; n < hi; n += 1024) {
        float v0 = row[n];
        float v1 = (n + 256 < hi) ? row[n + 256] : -1e30f;
        float v2 = (n + 512 < hi) ? row[n + 512] : -1e30f;
        float v3 = (n + 768 < hi) ? row[n + 768] : -1e30f;
        if (v0 >= thresh) exact(n);
        if (v1 >= thresh) exact(n + 256);
        if (v2 >= thresh) exact(n + 512);
        if (v3 >= thresh) exact(n + 768);
    }
#pragma unroll
    for (int o = 16; o > 0; o >>= 1) {
        ull other = __shfl_xor_sync(0xFFFFFFFFu, best, o);
        if (other > best) best = other;
    }
    if ((tid & 31) == 0 && best)
        atomicMax(&g_amaxE[t][m], best);
}

// ---------------- final h/c tail ----------------
__global__ void final_kernel(float* __restrict__ out, int out_size) {
    int idx = blockIdx.x * blockDim.x + threadIdx.x;
    const size_t base = (size_t)BB * TT * VOC;
    if ((size_t)out_size >= base + 2ull * BB * HIDD) {
        if (idx < BB * HIDD) {
            out[base + idx]             = g_hbuf[0][idx];
            out[base + BB * HIDD + idx] = g_cbuf[idx];
        }
    }
}

// ---------------- launch ----------------
extern "C" void kernel_launch(void* const* d_in, const int* in_sizes, int n_in,
                              void* d_out, int out_size) {
    const float* encoder_h = (const float*)d_in[0];
    const float* encoder_c = (const float*)d_in[1];
    const void*  target    = d_in[2];
    const int*   tf_mask   = (const int*)d_in[3];
    const float* embedding = (const float*)d_in[4];
    const float* w_ih      = (const float*)d_in[5];
    const float* w_hh      = (const float*)d_in[6];
    const float* b_ih      = (const float*)d_in[7];
    const float* b_hh      = (const float*)d_in[8];
    const float* fc_w      = (const float*)d_in[9];
    const float* fc_b      = (const float*)d_in[10];
    float* out = (float*)d_out;

    cudaFuncSetAttribute(gates_kernel,
                         cudaFuncAttributeMaxDynamicSharedMemorySize, G_SMEM_BYTES);
    cudaFuncSetAttribute(fc_mma_kernel,
                         cudaFuncAttributeMaxDynamicSharedMemorySize, FC_SMEM);

    init_kernel<<<128, 256>>>(encoder_h, encoder_c, (const int*)target);
    wsplit_kernel<<<8000, 256>>>(fc_w);
    for (int t = 0; t < TT; ++t) {
        gates_kernel<<<128, 256, G_SMEM_BYTES>>>(t, (const long long*)target,
                                                 (const int*)target, tf_mask, embedding,
                                                 w_ih, w_hh, b_ih, b_hh);
        fc_mma_kernel<<<125, 512, FC_SMEM>>>(t, fc_b, out);
        fixup_kernel<<<256, 256>>>(t, fc_w, fc_b, out);
    }
    final_kernel<<<128, 256>>>(out, out_size);
}